// round 13
// baseline (speedup 1.0000x reference)
#include <cuda_runtime.h>

// Patch2Im / fold (col2im) with averaging and crop.
// Input : x_patch [B=4, C=64, K=7, K=7, NH=85, NW=85] fp32 (row-major)
// Output: [B, C, 253, 253] fp32 (padded frame 259x259, crop 3 each side)
//
// v5 = v2 (direct immediate-offset gather, 21 loads/thread) + 3 rows/block.
// Lane (g, u): g = tid/85 selects output row h0+g, u = tid%85 is the
// column group owning ow = 3u+3+e (e=0,1,2). For kernel column j the
// output with e=j%3 reads patch column pw = u+1-j/3, so all 7 loads of a
// kernel-row plane sit at FIXED immediate offsets from (plane_base + u):
//   {+1, P+1, 2P+1, 3P, 4P, 5P, 6P-1},  P = 85*85.
// 255/256 lanes active, 32/32 resident warps/SM, and the 3 rows of one
// (bc) are a contiguous 759-float output span -> one coalesced store loop.
// Normalization counts are analytic (ni * nj from predicates).

namespace {
constexpr int K     = 7;
constexpr int NH    = 85;
constexpr int NW    = 85;
constexpr int PLANE = NH * NW;          // 7225
constexpr int SLAB  = K * K * PLANE;    // 354025 floats per (b,c) slab
constexpr int PAD   = 3;
constexpr int HO    = 253;
constexpr int WO    = 253;
constexpr int BC    = 4 * 64;
constexpr int TPB   = 256;
constexpr int RPB   = 3;                // rows per block
constexpr int NGRP  = (HO + RPB - 1) / RPB;   // 85 row groups
}

__global__ __launch_bounds__(TPB)
void patch2im_kernel(const float* __restrict__ xp, float* __restrict__ out)
{
    __shared__ float srow[RPB * WO];     // 759 staged output floats

    const int tid = threadIdx.x;
    const int bc  = blockIdx.y;
    const int h0  = blockIdx.x * RPB;

    const int g = tid / NW;              // 0..3 (3 = spare lane)
    const int u = tid - g * NW;          // 0..84

    const int h = h0 + g;
    const bool valid = (g < RPB) && (h < HO);

    if (valid) {
        const int oh = h + PAD;          // 3..255

        // Valid kernel-row plane offsets for this lane's row. ni is 2 or 3.
        int offi[3];
        int ni = 0;
        const int ri = oh % 3;
        #pragma unroll
        for (int s = 0; s < 3; ++s) {
            const int i = ri + 3 * s;
            if (i < K) {
                const int d = oh - i;
                if (d >= 0) {
                    const int ph = d / 3;
                    if (ph < NH) offi[ni++] = i * (K * PLANE) + ph * NW;
                }
            }
        }
        if (ni == 2) offi[2] = offi[1];  // safe address; loads predicated off

        const bool p2   = (ni == 3);
        const bool p012 = (u <= NW - 2); // pw = u+1 valid
        const bool p6   = (u >= 1);      // pw = u-1 valid

        const float* __restrict__ base = xp + (size_t)bc * SLAB + u;

        float a0 = 0.f, a1 = 0.f, a2 = 0.f;
        #pragma unroll
        for (int a = 0; a < 3; ++a) {
            const float* __restrict__ q = base + offi[a];
            const bool pa = (a < 2) || p2;
            if (pa && p012) {
                a0 += __ldcs(q + 1);                 // j=0
                a1 += __ldcs(q + PLANE + 1);         // j=1
                a2 += __ldcs(q + 2 * PLANE + 1);     // j=2
            }
            if (pa) {
                a0 += __ldcs(q + 3 * PLANE);         // j=3
                a1 += __ldcs(q + 4 * PLANE);         // j=4
                a2 += __ldcs(q + 5 * PLANE);         // j=5
            }
            if (pa && p6)
                a0 += __ldcs(q + 6 * PLANE - 1);     // j=6
        }

        // Analytic normalization: count = ni * nj.
        const int nj0  = 1 + (int)p012 + (int)p6;    // j in {0,3,6}
        const int nj12 = 1 + (int)p012;              // j in {1,4} / {2,5}
        const float inv0  = __fdividef(1.f, (float)(ni * nj0));
        const float inv12 = __fdividef(1.f, (float)(ni * nj12));
        a0 *= inv0;  a1 *= inv12;  a2 *= inv12;

        // Stage into the flat 3-row buffer (stride-3 STS, bank-clean).
        const int c0 = 3 * u;            // 0..252
        float* __restrict__ s = srow + g * WO;
        s[c0] = a0;                      // c0 <= 252 always valid
        if (c0 + 1 < WO) s[c0 + 1] = a1;
        if (c0 + 2 < WO) s[c0 + 2] = a2;
    }

    __syncthreads();

    // Rows h0..h0+nrows-1 of channel bc are one contiguous output span.
    const int nrows = (HO - h0 < RPB) ? (HO - h0) : RPB;
    const int total = nrows * WO;        // 759 (or 253 for the last group)
    float* __restrict__ o = out + ((size_t)bc * HO + h0) * WO;
    for (int w = tid; w < total; w += TPB)
        o[w] = srow[w];
}

extern "C" void kernel_launch(void* const* d_in, const int* in_sizes, int n_in,
                              void* d_out, int out_size)
{
    (void)in_sizes; (void)n_in; (void)out_size;
    const float* xp = (const float*)d_in[0];
    float* out = (float*)d_out;

    dim3 grid(NGRP, BC);   // 85 x 256
    dim3 block(TPB);
    patch2im_kernel<<<grid, block>>>(xp, out);
}

// round 14
// speedup vs baseline: 1.0814x; 1.0814x over previous
#include <cuda_runtime.h>

// Patch2Im / fold (col2im) with averaging and crop.
// Input : x_patch [B=4, C=64, K=7, K=7, NH=85, NW=85] fp32 (row-major)
// Output: [B, C, 253, 253] fp32 (padded frame 259x259, crop 3 each side)
//
// v6 = v2 (direct immediate-offset gather; best @66us) + deep load batching.
// Thread t owns output columns ow = 3t+3+e (e=0,1,2). For kernel column j,
// the output with e=j%3 reads patch column pw = t+1 - j/3, so all 7 loads
// of a kernel-row plane sit at FIXED immediate offsets from (plane_base+t):
//   {+1, P+1, 2P+1, 3P, 4P, 5P, 6P-1},  P = 85*85.
// All 21 loads are issued into a flat local array BEFORE any accumulation,
// and __launch_bounds__(96, 10) gives ptxas a 64-reg budget (still 10
// blocks/SM = 30 warps: warp-limited, not reg-limited) so the full stream
// stays in flight -> ~2x memory-level parallelism per warp vs v2.

namespace {
constexpr int K     = 7;
constexpr int NH    = 85;
constexpr int NW    = 85;
constexpr int PLANE = NH * NW;          // 7225
constexpr int PAD   = 3;
constexpr int HO    = 253;
constexpr int WO    = 253;
constexpr int BC    = 4 * 64;
constexpr int TPB   = 96;
constexpr int TGRP  = 85;
}

// Issue the 7 loads of one kernel-row plane into v[0..6] (predicated).
__device__ __forceinline__ void load_plane(const float* __restrict__ q,
                                           bool p012, bool p6, float* v)
{
    v[0] = p012 ? __ldcs(q + 1)             : 0.f;   // j=0, pw=t+1
    v[1] = p012 ? __ldcs(q + PLANE + 1)     : 0.f;   // j=1
    v[2] = p012 ? __ldcs(q + 2 * PLANE + 1) : 0.f;   // j=2
    v[3] = __ldcs(q + 3 * PLANE);                    // j=3, pw=t
    v[4] = __ldcs(q + 4 * PLANE);                    // j=4
    v[5] = __ldcs(q + 5 * PLANE);                    // j=5
    v[6] = p6 ? __ldcs(q + 6 * PLANE - 1)   : 0.f;   // j=6, pw=t-1
}

__global__ __launch_bounds__(TPB, 10)
void patch2im_kernel(const float* __restrict__ xp, float* __restrict__ out)
{
    const int h  = blockIdx.x;           // output row 0..252
    const int bc = blockIdx.y;           // fused batch*channel
    const int t  = threadIdx.x;          // 0..95

    __shared__ float sm[TGRP * 3];

    const int oh = h + PAD;              // padded row coord 3..255

    // Valid kernel-row plane offsets for this row (uniform per block).
    int offi[3];
    int ni = 0;
    const int ri = oh % 3;
    #pragma unroll
    for (int s = 0; s < 3; ++s) {
        const int i = ri + 3 * s;
        if (i < K) {
            const int d = oh - i;
            if (d >= 0) {
                const int ph = d / 3;
                if (ph < NH) offi[ni++] = i * (K * PLANE) + ph * NW;
            }
        }
    }
    // ni is always 2 or 3 for oh in [3, 255].

    if (t < TGRP) {
        const float* __restrict__ base =
            xp + (size_t)bc * (K * K * PLANE) + t;

        const bool p012 = (t <= NW - 2);   // t <= 83
        const bool p6   = (t >= 1);

        float a0, a1, a2;

        if (ni == 3) {                     // uniform branch (whole block)
            float v[21];
            load_plane(base + offi[0], p012, p6, v);
            load_plane(base + offi[1], p012, p6, v + 7);
            load_plane(base + offi[2], p012, p6, v + 14);

            a0 = (v[0] + v[3]) + (v[6] + v[7]) + (v[10] + v[13])
               + (v[14] + v[17]) + v[20];
            a1 = (v[1] + v[4]) + (v[8] + v[11]) + (v[15] + v[18]);
            a2 = (v[2] + v[5]) + (v[9] + v[12]) + (v[16] + v[19]);

            const float inv0  = (p012 && p6) ? (1.f / 9.f) : (1.f / 6.f);
            const float inv12 = p012 ? (1.f / 6.f) : (1.f / 3.f);
            a0 *= inv0;  a1 *= inv12;  a2 *= inv12;
        } else {
            float v[14];
            load_plane(base + offi[0], p012, p6, v);
            load_plane(base + offi[1], p012, p6, v + 7);

            a0 = (v[0] + v[3]) + (v[6] + v[7]) + (v[10] + v[13]);
            a1 = (v[1] + v[4]) + (v[8] + v[11]);
            a2 = (v[2] + v[5]) + (v[9] + v[12]);

            const float inv0  = (p012 && p6) ? (1.f / 6.f) : (1.f / 4.f);
            const float inv12 = p012 ? (1.f / 4.f) : (1.f / 2.f);
            a0 *= inv0;  a1 *= inv12;  a2 *= inv12;
        }

        // Stage: stride-3 STS, bank-conflict-free (gcd(3,32)=1).
        sm[3 * t + 0] = a0;
        sm[3 * t + 1] = a1;
        sm[3 * t + 2] = a2;
    }

    __syncthreads();

    // Coalesced row store: 253 floats with 96 threads, 3 passes.
    float* __restrict__ orow = out + ((size_t)bc * HO + h) * WO;
    #pragma unroll
    for (int idx = 0; idx < 3; ++idx) {
        const int w = t + idx * TPB;
        if (w < WO) orow[w] = sm[w];
    }
}

extern "C" void kernel_launch(void* const* d_in, const int* in_sizes, int n_in,
                              void* d_out, int out_size)
{
    (void)in_sizes; (void)n_in; (void)out_size;
    const float* xp = (const float*)d_in[0];
    float* out = (float*)d_out;

    dim3 grid(HO, BC);   // 253 x 256
    dim3 block(TPB);
    patch2im_kernel<<<grid, block>>>(xp, out);
}